// round 2
// baseline (speedup 1.0000x reference)
#include <cuda_runtime.h>

#define N_NODES  200000
#define N_GRAPHS 4000
#define N_EDGES  3200000

// ---------------- scratch (device globals; no allocation allowed) ----------
__device__ alignas(16) float g_deg[N_NODES];
__device__ alignas(16) float g_cnt[N_GRAPHS];
__device__ alignas(16) float g_msg1[N_NODES * 32];
__device__ alignas(16) float g_h1[N_NODES * 64];
__device__ alignas(16) float g_msg2[N_NODES * 64];

// ---------------- helpers ---------------------------------------------------
__device__ __forceinline__ void red_add_v4(float* p, float4 v) {
    unsigned long long gp = (unsigned long long)__cvta_generic_to_global((void*)p);
    asm volatile("red.global.add.v4.f32 [%0], {%1, %2, %3, %4};"
                 :: "l"(gp), "f"(v.x), "f"(v.y), "f"(v.z), "f"(v.w)
                 : "memory");
}

__device__ __forceinline__ void red_add_f32(float* p, float v) {
    unsigned long long gp = (unsigned long long)__cvta_generic_to_global((void*)p);
    asm volatile("red.global.add.f32 [%0], %1;" :: "l"(gp), "f"(v) : "memory");
}

// ---------------- zero scratch ----------------------------------------------
__global__ void zero_all_kernel() {
    int i = blockIdx.x * blockDim.x + threadIdx.x;   // float4 index
    float4 z = make_float4(0.f, 0.f, 0.f, 0.f);
    if (i < N_NODES * 8)  ((float4*)g_msg1)[i] = z;   // 1.6M
    if (i < N_NODES * 16) ((float4*)g_msg2)[i] = z;   // 3.2M
    if (i < N_NODES / 4)  ((float4*)g_deg)[i]  = z;
    if (i < N_GRAPHS / 4) ((float4*)g_cnt)[i]  = z;
}

__global__ void init_out_kernel(float* __restrict__ out,
                                const float* __restrict__ b_lin) {
    int i = blockIdx.x * blockDim.x + threadIdx.x;
    if (i < N_GRAPHS * 2) out[i] = b_lin[i & 1];
}

// ---------------- graph-count ------------------------------------------------
__global__ void cnt_kernel(const int* __restrict__ batch) {
    int i = blockIdx.x * blockDim.x + threadIdx.x;
    if (i < N_NODES) red_add_f32(&g_cnt[batch[i]], 1.0f);
}

// ---------------- edge aggregation ------------------------------------------
// layer 1: 32-wide features; 8 lanes per edge, one float4 each.
// lane 0 additionally accumulates the destination degree.
__global__ void agg1_kernel(const float4* __restrict__ x4,
                            const int* __restrict__ src,
                            const int* __restrict__ dst) {
    long t = (long)blockIdx.x * blockDim.x + threadIdx.x;
    int e = (int)(t >> 3);
    if (e >= N_EDGES) return;
    int q = (int)(t & 7);
    int s = src[e], d = dst[e];
    float4 v = x4[(long)s * 8 + q];
    red_add_v4(&g_msg1[(long)d * 32 + q * 4], v);
    if (q == 0) red_add_f32(&g_deg[d], 1.0f);
}

// layer 2: 64-wide features; 8 lanes per edge, two float4 each
__global__ void agg2_kernel(const int* __restrict__ src,
                            const int* __restrict__ dst) {
    long t = (long)blockIdx.x * blockDim.x + threadIdx.x;
    int e = (int)(t >> 3);
    if (e >= N_EDGES) return;
    int q = (int)(t & 7);
    int s = src[e], d = dst[e];
    const float4* h4 = (const float4*)g_h1;
    float4 v0 = h4[(long)s * 16 + q];
    float4 v1 = h4[(long)s * 16 + 8 + q];
    red_add_v4(&g_msg2[(long)d * 64 + q * 4], v0);
    red_add_v4(&g_msg2[(long)d * 64 + 32 + q * 4], v1);
}

// ---------------- layer-1 transform -----------------------------------------
// h1 = relu(mean(msg1) @ W1_l^T + b1 + x @ W1_r^T)
// block: 256 threads, 64-node tile; thread = 4 nodes x 4 outputs
#define PAD 68
__global__ void xform1_kernel(const float4* __restrict__ x4,
                              const float* __restrict__ W1l,
                              const float* __restrict__ b1,
                              const float* __restrict__ W1r) {
    extern __shared__ float sm[];
    float* Ws  = sm;               // [64][PAD]  transposed combined weights
    float* ins = sm + 64 * PAD;    // [64][PAD]  inputs [k][node]
    float* bsh = sm + 2 * 64 * PAD;

    int tid = threadIdx.x;
    int nb = blockIdx.x * 64;

    for (int idx = tid; idx < 64 * 32; idx += 256) {
        int j = idx >> 5, k = idx & 31;
        Ws[k * PAD + j]        = W1l[idx];
        Ws[(k + 32) * PAD + j] = W1r[idx];
    }
    if (tid < 64) bsh[tid] = b1[tid];

    for (int idx = tid; idx < 512; idx += 256) {
        int n = idx >> 3, q = idx & 7;
        int node = nb + n;
        float r = 1.0f / fmaxf(g_deg[node], 1.0f);
        float4 m = ((const float4*)g_msg1)[(long)node * 8 + q];
        ins[(q * 4 + 0) * PAD + n] = m.x * r;
        ins[(q * 4 + 1) * PAD + n] = m.y * r;
        ins[(q * 4 + 2) * PAD + n] = m.z * r;
        ins[(q * 4 + 3) * PAD + n] = m.w * r;
        float4 xv = x4[(long)node * 8 + q];
        ins[(32 + q * 4 + 0) * PAD + n] = xv.x;
        ins[(32 + q * 4 + 1) * PAD + n] = xv.y;
        ins[(32 + q * 4 + 2) * PAD + n] = xv.z;
        ins[(32 + q * 4 + 3) * PAD + n] = xv.w;
    }
    __syncthreads();

    int tx = tid & 15, ty = tid >> 4;
    float acc[4][4];
#pragma unroll
    for (int j = 0; j < 4; j++) {
        float b = bsh[tx * 4 + j];
        acc[0][j] = b; acc[1][j] = b; acc[2][j] = b; acc[3][j] = b;
    }

#pragma unroll 8
    for (int k = 0; k < 64; k++) {
        float4 a = *(const float4*)&ins[k * PAD + ty * 4];
        float4 w = *(const float4*)&Ws[k * PAD + tx * 4];
        float av[4] = {a.x, a.y, a.z, a.w};
        float wv[4] = {w.x, w.y, w.z, w.w};
#pragma unroll
        for (int i = 0; i < 4; i++)
#pragma unroll
            for (int j = 0; j < 4; j++)
                acc[i][j] += av[i] * wv[j];
    }

#pragma unroll
    for (int i = 0; i < 4; i++) {
        int node = nb + ty * 4 + i;
        float4 o;
        o.x = fmaxf(acc[i][0], 0.f);
        o.y = fmaxf(acc[i][1], 0.f);
        o.z = fmaxf(acc[i][2], 0.f);
        o.w = fmaxf(acc[i][3], 0.f);
        *(float4*)&g_h1[(long)node * 64 + tx * 4] = o;
    }
}

// ---------------- layer-2 transform + fused pooling -------------------------
// h2 = relu(mean(msg2) @ W2_l^T + b2 + h1 @ W2_r^T)
// out[g] += (h2 . W_lin_row) / cnt[g]
__global__ void xform2_kernel(const float* __restrict__ W2l,
                              const float* __restrict__ b2,
                              const float* __restrict__ W2r,
                              const float* __restrict__ Wlin,
                              const int* __restrict__ batch,
                              float* __restrict__ out) {
    extern __shared__ float sm[];
    float* Ws   = sm;                 // [128][PAD]
    float* ins  = sm + 128 * PAD;     // [128][PAD]; reused as hs[64][PAD]
    float* bsh  = sm + 2 * 128 * PAD; // 64
    float* wlin = bsh + 64;           // 128

    int tid = threadIdx.x;
    int nb = blockIdx.x * 64;

    for (int idx = tid; idx < 64 * 64; idx += 256) {
        int j = idx >> 6, k = idx & 63;
        Ws[k * PAD + j]        = W2l[idx];
        Ws[(k + 64) * PAD + j] = W2r[idx];
    }
    if (tid < 64) bsh[tid] = b2[tid];
    if (tid < 128) wlin[tid] = Wlin[tid];

    // stage mean(msg2) into rows [0,64), h1 into rows [64,128)
    for (int idx = tid; idx < 1024; idx += 256) {
        int n = idx >> 4, q = idx & 15;
        int node = nb + n;
        float r = 1.0f / fmaxf(g_deg[node], 1.0f);
        float4 m = ((const float4*)g_msg2)[(long)node * 16 + q];
        ins[(q * 4 + 0) * PAD + n] = m.x * r;
        ins[(q * 4 + 1) * PAD + n] = m.y * r;
        ins[(q * 4 + 2) * PAD + n] = m.z * r;
        ins[(q * 4 + 3) * PAD + n] = m.w * r;
        float4 h = ((const float4*)g_h1)[(long)node * 16 + q];
        ins[(64 + q * 4 + 0) * PAD + n] = h.x;
        ins[(64 + q * 4 + 1) * PAD + n] = h.y;
        ins[(64 + q * 4 + 2) * PAD + n] = h.z;
        ins[(64 + q * 4 + 3) * PAD + n] = h.w;
    }
    __syncthreads();

    int tx = tid & 15, ty = tid >> 4;
    float acc[4][4];
#pragma unroll
    for (int j = 0; j < 4; j++) {
        float b = bsh[tx * 4 + j];
        acc[0][j] = b; acc[1][j] = b; acc[2][j] = b; acc[3][j] = b;
    }

#pragma unroll 8
    for (int k = 0; k < 128; k++) {
        float4 a = *(const float4*)&ins[k * PAD + ty * 4];
        float4 w = *(const float4*)&Ws[k * PAD + tx * 4];
        float av[4] = {a.x, a.y, a.z, a.w};
        float wv[4] = {w.x, w.y, w.z, w.w};
#pragma unroll
        for (int i = 0; i < 4; i++)
#pragma unroll
            for (int j = 0; j < 4; j++)
                acc[i][j] += av[i] * wv[j];
    }

    __syncthreads();   // everyone done reading ins before we overwrite it

    // write relu(h2) into shared as hs[n][k]
#pragma unroll
    for (int i = 0; i < 4; i++) {
        int n = ty * 4 + i;
        float4 o;
        o.x = fmaxf(acc[i][0], 0.f);
        o.y = fmaxf(acc[i][1], 0.f);
        o.z = fmaxf(acc[i][2], 0.f);
        o.w = fmaxf(acc[i][3], 0.f);
        *(float4*)&ins[n * PAD + tx * 4] = o;
    }
    __syncthreads();

    // fused global mean pool + linear head: 2 atomics per node
    if (tid < 128) {
        int n = tid >> 1, o = tid & 1;
        int node = nb + n;
        float y = 0.f;
#pragma unroll 8
        for (int k = 0; k < 64; k++)
            y += ins[n * PAD + k] * wlin[o * 64 + k];
        int g = batch[node];
        float c = fmaxf(g_cnt[g], 1.0f);
        red_add_f32(&out[g * 2 + o], y / c);
    }
}

// ---------------- launch -----------------------------------------------------
extern "C" void kernel_launch(void* const* d_in, const int* in_sizes, int n_in,
                              void* d_out, int out_size) {
    (void)in_sizes; (void)n_in; (void)out_size;
    const float* x    = (const float*)d_in[0];
    const int*   ei   = (const int*)d_in[1];
    const int*   batch= (const int*)d_in[2];
    const float* W1l  = (const float*)d_in[3];
    const float* b1   = (const float*)d_in[4];
    const float* W1r  = (const float*)d_in[5];
    const float* W2l  = (const float*)d_in[6];
    const float* b2   = (const float*)d_in[7];
    const float* W2r  = (const float*)d_in[8];
    const float* Wlin = (const float*)d_in[9];
    const float* blin = (const float*)d_in[10];
    float* out = (float*)d_out;

    const int* src = ei;
    const int* dst = ei + N_EDGES;

    const int SMEM1 = (2 * 64 * PAD + 64) * 4;          // ~35 KB
    const int SMEM2 = (2 * 128 * PAD + 64 + 128) * 4;   // ~70 KB
    cudaFuncSetAttribute(xform1_kernel, cudaFuncAttributeMaxDynamicSharedMemorySize, SMEM1);
    cudaFuncSetAttribute(xform2_kernel, cudaFuncAttributeMaxDynamicSharedMemorySize, SMEM2);

    zero_all_kernel<<<12500, 256>>>();                       // covers 3.2M float4
    init_out_kernel<<<(N_GRAPHS * 2 + 255) / 256, 256>>>(out, blin);
    cnt_kernel<<<(N_NODES + 255) / 256, 256>>>(batch);
    agg1_kernel<<<(N_EDGES * 8) / 256, 256>>>((const float4*)x, src, dst);
    xform1_kernel<<<N_NODES / 64, 256, SMEM1>>>((const float4*)x, W1l, b1, W1r);
    agg2_kernel<<<(N_EDGES * 8) / 256, 256>>>(src, dst);
    xform2_kernel<<<N_NODES / 64, 256, SMEM2>>>(W2l, b2, W2r, Wlin, batch, out);
}

// round 4
// speedup vs baseline: 1.1280x; 1.1280x over previous
#include <cuda_runtime.h>

#define N_NODES  200000
#define N_GRAPHS 4000
#define N_EDGES  3200000
#define NTILES   3125        /* N_NODES / 64 */
#define SCAN_BLOCKS 196      /* ceil(N_NODES / 1024) */

// ---------------- scratch (device globals; no allocation allowed) -----------
__device__ int   g_hcnt[N_NODES];
__device__ int   g_off[N_NODES + 1];
__device__ int   g_cur[N_NODES];
__device__ int   g_bsum[SCAN_BLOCKS];
__device__ int   g_bbase[SCAN_BLOCKS];
__device__ int   g_ssrc[N_EDGES];
__device__ float g_cnt[N_GRAPHS];
__device__ __align__(16) float g_h1[N_NODES * 64];

// ---------------- asm helpers ------------------------------------------------
__device__ __forceinline__ void red_add_f32(float* p, float v) {
    unsigned long long gp = (unsigned long long)__cvta_generic_to_global((void*)p);
    asm volatile("red.global.add.f32 [%0], %1;" :: "l"(gp), "f"(v) : "memory");
}
__device__ __forceinline__ void red_add_u32(int* p, unsigned v) {
    unsigned long long gp = (unsigned long long)__cvta_generic_to_global((void*)p);
    asm volatile("red.global.add.u32 [%0], %1;" :: "l"(gp), "r"(v) : "memory");
}
__device__ __forceinline__ unsigned long long pack2(float lo, float hi) {
    unsigned long long r;
    asm("mov.b64 %0, {%1, %2};" : "=l"(r) : "f"(lo), "f"(hi));
    return r;
}
__device__ __forceinline__ float2 unpack2(unsigned long long v) {
    float2 r;
    asm("mov.b64 {%0, %1}, %2;" : "=f"(r.x), "=f"(r.y) : "l"(v));
    return r;
}
__device__ __forceinline__ void ffma2(unsigned long long& acc,
                                      unsigned long long a, unsigned long long b) {
    asm("fma.rn.f32x2 %0, %1, %2, %0;" : "+l"(acc) : "l"(a), "l"(b));
}

// ---------------- small init kernels -----------------------------------------
__global__ void zero_small_kernel() {
    int i = blockIdx.x * blockDim.x + threadIdx.x;
    if (i < N_NODES / 4)  ((int4*)g_hcnt)[i] = make_int4(0, 0, 0, 0);
    if (i < N_GRAPHS / 4) ((float4*)g_cnt)[i] = make_float4(0.f, 0.f, 0.f, 0.f);
}

__global__ void init_out_kernel(float* __restrict__ out,
                                const float* __restrict__ b_lin) {
    int i = blockIdx.x * blockDim.x + threadIdx.x;
    if (i < N_GRAPHS * 2) out[i] = b_lin[i & 1];
}

__global__ void cnt_kernel(const int* __restrict__ batch) {
    int i = blockIdx.x * blockDim.x + threadIdx.x;
    if (i < N_NODES) red_add_f32(&g_cnt[batch[i]], 1.0f);
}

// ---------------- CSR build: hist -> scan -> scatter -------------------------
__global__ void hist_kernel(const int* __restrict__ dst) {
    int e = blockIdx.x * blockDim.x + threadIdx.x;
    if (e < N_EDGES) red_add_u32(&g_hcnt[dst[e]], 1u);
}

__global__ void scanA_kernel() {   // per-block totals over 1024-count chunks
    __shared__ int sh[256];
    int b = blockIdx.x, t = threadIdx.x;
    int i0 = b * 1024 + t * 4, s = 0;
#pragma unroll
    for (int i = 0; i < 4; i++) {
        int idx = i0 + i;
        s += (idx < N_NODES) ? g_hcnt[idx] : 0;
    }
    sh[t] = s; __syncthreads();
    for (int d = 128; d > 0; d >>= 1) {
        if (t < d) sh[t] += sh[t + d];
        __syncthreads();
    }
    if (t == 0) g_bsum[b] = sh[0];
}

__global__ void scanB_kernel() {   // exclusive scan of block totals
    __shared__ int sh[256];
    int t = threadIdx.x;
    sh[t] = (t < SCAN_BLOCKS) ? g_bsum[t] : 0;
    __syncthreads();
    for (int d = 1; d < 256; d <<= 1) {
        int u = (t >= d) ? sh[t - d] : 0;
        __syncthreads();
        sh[t] += u;
        __syncthreads();
    }
    if (t < SCAN_BLOCKS) g_bbase[t] = t ? sh[t - 1] : 0;
    if (t == 0) g_off[N_NODES] = N_EDGES;
}

__global__ void scanC_kernel() {   // final offsets + cursor copy
    __shared__ int sh[256];
    int b = blockIdx.x, t = threadIdx.x;
    int i0 = b * 1024 + t * 4;
    int c[4], s = 0;
#pragma unroll
    for (int i = 0; i < 4; i++) {
        int idx = i0 + i;
        c[i] = (idx < N_NODES) ? g_hcnt[idx] : 0;
        s += c[i];
    }
    sh[t] = s; __syncthreads();
    for (int d = 1; d < 256; d <<= 1) {
        int u = (t >= d) ? sh[t - d] : 0;
        __syncthreads();
        sh[t] += u;
        __syncthreads();
    }
    int run = g_bbase[b] + (t ? sh[t - 1] : 0);
#pragma unroll
    for (int i = 0; i < 4; i++) {
        int idx = i0 + i;
        if (idx < N_NODES) {
            g_off[idx] = run;
            g_cur[idx] = run;
            run += c[i];
        }
    }
}

__global__ void scatter_kernel(const int* __restrict__ src,
                               const int* __restrict__ dst) {
    int e = blockIdx.x * blockDim.x + threadIdx.x;
    if (e < N_EDGES) {
        int pos = atomicAdd(&g_cur[dst[e]], 1);
        g_ssrc[pos] = src[e];
    }
}

// ---------------- fused layer 1: CSR gather-mean + GEMM + relu ---------------
// block = 256 threads, 64-node tile. Warp w owns nodes [w*8, w*8+8).
// sacc layout [k][68]: rows 0..31 = mean(msg), rows 32..63 = self x.
__global__ void __launch_bounds__(256) fused1_kernel(
        const float* __restrict__ x,
        const float* __restrict__ W1l,
        const float* __restrict__ b1,
        const float* __restrict__ W1r) {
    __shared__ __align__(16) float Ws[64 * 68];
    __shared__ __align__(16) float sacc[64 * 68];
    __shared__ float bsh[64];

    int tid = threadIdx.x;
    int nb = blockIdx.x * 64;

    for (int idx = tid; idx < 2048; idx += 256) {
        int j = idx >> 5, k = idx & 31;
        Ws[k * 68 + j]        = W1l[idx];
        Ws[(k + 32) * 68 + j] = W1r[idx];
    }
    if (tid < 64) bsh[tid] = b1[tid];

    const float4* x4 = (const float4*)x;
    for (int idx = tid; idx < 512; idx += 256) {
        int n = idx >> 3, q = idx & 7;
        float4 v = x4[(nb + n) * 8 + q];
        sacc[(32 + q * 4 + 0) * 68 + n] = v.x;
        sacc[(32 + q * 4 + 1) * 68 + n] = v.y;
        sacc[(32 + q * 4 + 2) * 68 + n] = v.z;
        sacc[(32 + q * 4 + 3) * 68 + n] = v.w;
    }

    int warp = tid >> 5, lane = tid & 31;
#pragma unroll 1
    for (int i = 0; i < 8; i++) {
        int n = nb + warp * 8 + i;
        int beg = g_off[n], end = g_off[n + 1];
        float a0 = 0.f, a1 = 0.f, a2 = 0.f, a3 = 0.f;
        int e = beg;
        for (; e + 4 <= end; e += 4) {
            int s0 = g_ssrc[e], s1 = g_ssrc[e + 1];
            int s2 = g_ssrc[e + 2], s3 = g_ssrc[e + 3];
            a0 += x[s0 * 32 + lane];
            a1 += x[s1 * 32 + lane];
            a2 += x[s2 * 32 + lane];
            a3 += x[s3 * 32 + lane];
        }
        for (; e < end; e++) a0 += x[g_ssrc[e] * 32 + lane];
        float m = (a0 + a1) + (a2 + a3);
        m *= 1.0f / fmaxf((float)(end - beg), 1.0f);
        sacc[lane * 68 + warp * 8 + i] = m;
    }
    __syncthreads();

    // GEMM: out[n][j] = sum_k sacc[k][n] * Ws[k][j] + b, with packed FFMA2
    int tx = tid & 15, ty = tid >> 4;
    unsigned long long acc2[4][2];
    {
        unsigned long long b01 = pack2(bsh[tx * 4 + 0], bsh[tx * 4 + 1]);
        unsigned long long b23 = pack2(bsh[tx * 4 + 2], bsh[tx * 4 + 3]);
#pragma unroll
        for (int i = 0; i < 4; i++) { acc2[i][0] = b01; acc2[i][1] = b23; }
    }
#pragma unroll 8
    for (int k = 0; k < 64; k++) {
        float4  a  = *(const float4*)&sacc[k * 68 + ty * 4];
        double2 wd = *(const double2*)&Ws[k * 68 + tx * 4];
        unsigned long long w01 = __double_as_longlong(wd.x);
        unsigned long long w23 = __double_as_longlong(wd.y);
        unsigned long long p;
        p = pack2(a.x, a.x); ffma2(acc2[0][0], p, w01); ffma2(acc2[0][1], p, w23);
        p = pack2(a.y, a.y); ffma2(acc2[1][0], p, w01); ffma2(acc2[1][1], p, w23);
        p = pack2(a.z, a.z); ffma2(acc2[2][0], p, w01); ffma2(acc2[2][1], p, w23);
        p = pack2(a.w, a.w); ffma2(acc2[3][0], p, w01); ffma2(acc2[3][1], p, w23);
    }
#pragma unroll
    for (int i = 0; i < 4; i++) {
        float2 p0 = unpack2(acc2[i][0]);
        float2 p1 = unpack2(acc2[i][1]);
        float4 o;
        o.x = fmaxf(p0.x, 0.f); o.y = fmaxf(p0.y, 0.f);
        o.z = fmaxf(p1.x, 0.f); o.w = fmaxf(p1.y, 0.f);
        ((float4*)g_h1)[(nb + ty * 4 + i) * 16 + tx] = o;
    }
}

// ---------------- fused layer 2: CSR gather-mean + GEMM + relu + pool --------
// dynamic smem: Ws[128][68] | sacc[128][68] | bsh[64] | wlin[128]
__global__ void __launch_bounds__(256) fused2_kernel(
        const float* __restrict__ W2l,
        const float* __restrict__ b2,
        const float* __restrict__ W2r,
        const float* __restrict__ Wlin,
        const int* __restrict__ batch,
        float* __restrict__ out) {
    extern __shared__ __align__(16) float sm[];
    float* Ws   = sm;                // 128*68
    float* sacc = sm + 128 * 68;     // 128*68 ; later reused as hs[64][68]
    float* bsh  = sacc + 128 * 68;   // 64
    float* wlin = bsh + 64;          // 128

    int tid = threadIdx.x;
    int nb = blockIdx.x * 64;

    for (int idx = tid; idx < 4096; idx += 256) {
        int j = idx >> 6, k = idx & 63;
        Ws[k * 68 + j]        = W2l[idx];
        Ws[(k + 64) * 68 + j] = W2r[idx];
    }
    if (tid < 64)  bsh[tid]  = b2[tid];
    if (tid < 128) wlin[tid] = Wlin[tid];

    const float4* h4 = (const float4*)g_h1;
    for (int idx = tid; idx < 1024; idx += 256) {
        int n = idx >> 4, q = idx & 15;
        float4 v = h4[(nb + n) * 16 + q];
        sacc[(64 + q * 4 + 0) * 68 + n] = v.x;
        sacc[(64 + q * 4 + 1) * 68 + n] = v.y;
        sacc[(64 + q * 4 + 2) * 68 + n] = v.z;
        sacc[(64 + q * 4 + 3) * 68 + n] = v.w;
    }

    int warp = tid >> 5, lane = tid & 31;
#pragma unroll 1
    for (int i = 0; i < 8; i++) {
        int n = nb + warp * 8 + i;
        int beg = g_off[n], end = g_off[n + 1];
        float a0 = 0.f, a1 = 0.f, c0 = 0.f, c1 = 0.f;
        int e = beg;
        for (; e + 2 <= end; e += 2) {
            int s0 = g_ssrc[e], s1 = g_ssrc[e + 1];
            a0 += g_h1[s0 * 64 + lane];
            c0 += g_h1[s0 * 64 + 32 + lane];
            a1 += g_h1[s1 * 64 + lane];
            c1 += g_h1[s1 * 64 + 32 + lane];
        }
        if (e < end) {
            int s0 = g_ssrc[e];
            a0 += g_h1[s0 * 64 + lane];
            c0 += g_h1[s0 * 64 + 32 + lane];
        }
        float r = 1.0f / fmaxf((float)(end - beg), 1.0f);
        sacc[lane * 68 + warp * 8 + i]        = (a0 + a1) * r;
        sacc[(lane + 32) * 68 + warp * 8 + i] = (c0 + c1) * r;
    }
    __syncthreads();

    int tx = tid & 15, ty = tid >> 4;
    unsigned long long acc2[4][2];
    {
        unsigned long long b01 = pack2(bsh[tx * 4 + 0], bsh[tx * 4 + 1]);
        unsigned long long b23 = pack2(bsh[tx * 4 + 2], bsh[tx * 4 + 3]);
#pragma unroll
        for (int i = 0; i < 4; i++) { acc2[i][0] = b01; acc2[i][1] = b23; }
    }
#pragma unroll 8
    for (int k = 0; k < 128; k++) {
        float4  a  = *(const float4*)&sacc[k * 68 + ty * 4];
        double2 wd = *(const double2*)&Ws[k * 68 + tx * 4];
        unsigned long long w01 = __double_as_longlong(wd.x);
        unsigned long long w23 = __double_as_longlong(wd.y);
        unsigned long long p;
        p = pack2(a.x, a.x); ffma2(acc2[0][0], p, w01); ffma2(acc2[0][1], p, w23);
        p = pack2(a.y, a.y); ffma2(acc2[1][0], p, w01); ffma2(acc2[1][1], p, w23);
        p = pack2(a.z, a.z); ffma2(acc2[2][0], p, w01); ffma2(acc2[2][1], p, w23);
        p = pack2(a.w, a.w); ffma2(acc2[3][0], p, w01); ffma2(acc2[3][1], p, w23);
    }
    __syncthreads();   // all GEMM reads of sacc done before reuse as hs

    // write relu(h2) into hs[n][k] = sacc[n*68 + k]
#pragma unroll
    for (int i = 0; i < 4; i++) {
        float2 p0 = unpack2(acc2[i][0]);
        float2 p1 = unpack2(acc2[i][1]);
        float4 o;
        o.x = fmaxf(p0.x, 0.f); o.y = fmaxf(p0.y, 0.f);
        o.z = fmaxf(p1.x, 0.f); o.w = fmaxf(p1.y, 0.f);
        *(float4*)&sacc[(ty * 4 + i) * 68 + tx * 4] = o;
    }
    __syncthreads();

    // fused global mean pool + linear head: 2 atomics per node
    if (tid < 128) {
        int n = tid >> 1, o = tid & 1;
        float y = 0.f;
#pragma unroll 8
        for (int k = 0; k < 64; k++)
            y += sacc[n * 68 + k] * wlin[o * 64 + k];
        int g = batch[nb + n];
        float c = fmaxf(g_cnt[g], 1.0f);
        red_add_f32(&out[g * 2 + o], y / c);
    }
}

// ---------------- launch -----------------------------------------------------
extern "C" void kernel_launch(void* const* d_in, const int* in_sizes, int n_in,
                              void* d_out, int out_size) {
    (void)in_sizes; (void)n_in; (void)out_size;
    const float* x    = (const float*)d_in[0];
    const int*   ei   = (const int*)d_in[1];
    const int*   batch= (const int*)d_in[2];
    const float* W1l  = (const float*)d_in[3];
    const float* b1   = (const float*)d_in[4];
    const float* W1r  = (const float*)d_in[5];
    const float* W2l  = (const float*)d_in[6];
    const float* b2   = (const float*)d_in[7];
    const float* W2r  = (const float*)d_in[8];
    const float* Wlin = (const float*)d_in[9];
    const float* blin = (const float*)d_in[10];
    float* out = (float*)d_out;

    const int* src = ei;
    const int* dst = ei + N_EDGES;

    const int SMEM2 = (2 * 128 * 68 + 64 + 128) * 4;   // 70400 B
    cudaFuncSetAttribute(fused2_kernel, cudaFuncAttributeMaxDynamicSharedMemorySize, SMEM2);

    zero_small_kernel<<<(N_NODES / 4 + 255) / 256, 256>>>();
    init_out_kernel<<<(N_GRAPHS * 2 + 255) / 256, 256>>>(out, blin);
    cnt_kernel<<<(N_NODES + 255) / 256, 256>>>(batch);
    hist_kernel<<<N_EDGES / 256, 256>>>(dst);
    scanA_kernel<<<SCAN_BLOCKS, 256>>>();
    scanB_kernel<<<1, 256>>>();
    scanC_kernel<<<SCAN_BLOCKS, 256>>>();
    scatter_kernel<<<N_EDGES / 256, 256>>>(src, dst);
    fused1_kernel<<<NTILES, 256>>>(x, W1l, b1, W1r);
    fused2_kernel<<<NTILES, 256, SMEM2>>>(W2l, b2, W2r, Wlin, batch, out);
}

// round 6
// speedup vs baseline: 1.1834x; 1.0492x over previous
#include <cuda_runtime.h>

#define N_NODES  200000
#define N_GRAPHS 4000
#define N_EDGES  3200000
#define NTILES   3125        /* N_NODES / 64 */
#define SCAN_BLOCKS 196      /* ceil(N_NODES / 1024) */

// ---------------- scratch (device globals; no allocation allowed) -----------
__device__ int   g_hcnt[N_NODES];
__device__ int   g_off[N_NODES + 1];
__device__ int   g_cur[N_NODES];
__device__ int   g_bsum[SCAN_BLOCKS];
__device__ int   g_bbase[SCAN_BLOCKS];
__device__ int   g_ssrc[N_EDGES];
__device__ float g_cnt[N_GRAPHS];
__device__ __align__(16) float g_h1[N_NODES * 64];

// ---------------- asm helpers ------------------------------------------------
__device__ __forceinline__ void red_add_f32(float* p, float v) {
    unsigned long long gp = (unsigned long long)__cvta_generic_to_global((void*)p);
    asm volatile("red.global.add.f32 [%0], %1;" :: "l"(gp), "f"(v) : "memory");
}
__device__ __forceinline__ void red_add_u32(int* p, unsigned v) {
    unsigned long long gp = (unsigned long long)__cvta_generic_to_global((void*)p);
    asm volatile("red.global.add.u32 [%0], %1;" :: "l"(gp), "r"(v) : "memory");
}
__device__ __forceinline__ unsigned long long pack2(float lo, float hi) {
    unsigned long long r;
    asm("mov.b64 %0, {%1, %2};" : "=l"(r) : "f"(lo), "f"(hi));
    return r;
}
__device__ __forceinline__ float2 unpack2(unsigned long long v) {
    float2 r;
    asm("mov.b64 {%0, %1}, %2;" : "=f"(r.x), "=f"(r.y) : "l"(v));
    return r;
}
__device__ __forceinline__ void ffma2(unsigned long long& acc,
                                      unsigned long long a, unsigned long long b) {
    asm("fma.rn.f32x2 %0, %1, %2, %0;" : "+l"(acc) : "l"(a), "l"(b));
}

// ---------------- init kernels ------------------------------------------------
__global__ void init_kernel(float* __restrict__ out,
                            const float* __restrict__ b_lin) {
    int i = blockIdx.x * blockDim.x + threadIdx.x;
    if (i < N_NODES / 4)  ((int4*)g_hcnt)[i] = make_int4(0, 0, 0, 0);
    if (i < N_GRAPHS / 4) ((float4*)g_cnt)[i] = make_float4(0.f, 0.f, 0.f, 0.f);
    if (i < N_GRAPHS * 2) out[i] = b_lin[i & 1];
}

// batch is sorted: aggregate runs within each int4 before RED
__global__ void cnt_kernel(const int* __restrict__ batch) {
    int i = blockIdx.x * blockDim.x + threadIdx.x;
    if (i >= N_NODES / 4) return;
    int4 b = ((const int4*)batch)[i];
    int gcur = b.x; float c = 1.f;
    int v[3] = {b.y, b.z, b.w};
#pragma unroll
    for (int k = 0; k < 3; k++) {
        if (v[k] == gcur) c += 1.f;
        else { red_add_f32(&g_cnt[gcur], c); gcur = v[k]; c = 1.f; }
    }
    red_add_f32(&g_cnt[gcur], c);
}

// ---------------- CSR build: hist -> scan -> scatter -------------------------
__global__ void hist_kernel(const int* __restrict__ dst) {
    int i = blockIdx.x * blockDim.x + threadIdx.x;
    if (i >= N_EDGES / 4) return;
    int4 d = ((const int4*)dst)[i];
    red_add_u32(&g_hcnt[d.x], 1u);
    red_add_u32(&g_hcnt[d.y], 1u);
    red_add_u32(&g_hcnt[d.z], 1u);
    red_add_u32(&g_hcnt[d.w], 1u);
}

__global__ void scanA_kernel() {   // per-block totals over 1024-count chunks
    __shared__ int sh[256];
    int b = blockIdx.x, t = threadIdx.x;
    int i0 = b * 1024 + t * 4, s = 0;
#pragma unroll
    for (int i = 0; i < 4; i++) {
        int idx = i0 + i;
        s += (idx < N_NODES) ? g_hcnt[idx] : 0;
    }
    sh[t] = s; __syncthreads();
    for (int d = 128; d > 0; d >>= 1) {
        if (t < d) sh[t] += sh[t + d];
        __syncthreads();
    }
    if (t == 0) g_bsum[b] = sh[0];
}

__global__ void scanB_kernel() {   // exclusive scan of block totals
    __shared__ int sh[256];
    int t = threadIdx.x;
    sh[t] = (t < SCAN_BLOCKS) ? g_bsum[t] : 0;
    __syncthreads();
    for (int d = 1; d < 256; d <<= 1) {
        int u = (t >= d) ? sh[t - d] : 0;
        __syncthreads();
        sh[t] += u;
        __syncthreads();
    }
    if (t < SCAN_BLOCKS) g_bbase[t] = t ? sh[t - 1] : 0;
    if (t == 0) g_off[N_NODES] = N_EDGES;
}

__global__ void scanC_kernel() {   // final offsets + cursor copy
    __shared__ int sh[256];
    int b = blockIdx.x, t = threadIdx.x;
    int i0 = b * 1024 + t * 4;
    int c[4], s = 0;
#pragma unroll
    for (int i = 0; i < 4; i++) {
        int idx = i0 + i;
        c[i] = (idx < N_NODES) ? g_hcnt[idx] : 0;
        s += c[i];
    }
    sh[t] = s; __syncthreads();
    for (int d = 1; d < 256; d <<= 1) {
        int u = (t >= d) ? sh[t - d] : 0;
        __syncthreads();
        sh[t] += u;
        __syncthreads();
    }
    int run = g_bbase[b] + (t ? sh[t - 1] : 0);
#pragma unroll
    for (int i = 0; i < 4; i++) {
        int idx = i0 + i;
        if (idx < N_NODES) {
            g_off[idx] = run;
            g_cur[idx] = run;
            run += c[i];
        }
    }
}

__global__ void scatter_kernel(const int* __restrict__ src,
                               const int* __restrict__ dst) {
    int i = blockIdx.x * blockDim.x + threadIdx.x;
    if (i >= N_EDGES / 4) return;
    int4 s = ((const int4*)src)[i];
    int4 d = ((const int4*)dst)[i];
    g_ssrc[atomicAdd(&g_cur[d.x], 1)] = s.x;
    g_ssrc[atomicAdd(&g_cur[d.y], 1)] = s.y;
    g_ssrc[atomicAdd(&g_cur[d.z], 1)] = s.z;
    g_ssrc[atomicAdd(&g_cur[d.w], 1)] = s.w;
}

// ---------------- fused layer 1: CSR gather-mean + GEMM + relu ---------------
// block = 256 threads, 64-node tile. Warp w owns nodes [w*8, w*8+8).
// Gather: 4 lane-groups of 8; group g handles edge e+g, lane handles chunk ql.
// sacc layout [k][68]: rows 0..31 = mean(msg), rows 32..63 = self x.
__global__ void __launch_bounds__(256) fused1_kernel(
        const float* __restrict__ x,
        const float* __restrict__ W1l,
        const float* __restrict__ b1,
        const float* __restrict__ W1r) {
    __shared__ __align__(16) float Ws[64 * 68];
    __shared__ __align__(16) float sacc[64 * 68];
    __shared__ float bsh[64];

    int tid = threadIdx.x;
    int nb = blockIdx.x * 64;

    for (int idx = tid; idx < 2048; idx += 256) {
        int j = idx >> 5, k = idx & 31;
        Ws[k * 68 + j]        = W1l[idx];
        Ws[(k + 32) * 68 + j] = W1r[idx];
    }
    if (tid < 64) bsh[tid] = b1[tid];

    const float4* x4 = (const float4*)x;
    for (int idx = tid; idx < 512; idx += 256) {
        int n = idx >> 3, q = idx & 7;
        float4 v = x4[(nb + n) * 8 + q];
        sacc[(32 + q * 4 + 0) * 68 + n] = v.x;
        sacc[(32 + q * 4 + 1) * 68 + n] = v.y;
        sacc[(32 + q * 4 + 2) * 68 + n] = v.z;
        sacc[(32 + q * 4 + 3) * 68 + n] = v.w;
    }

    int warp = tid >> 5, lane = tid & 31;
    int g = lane >> 3, ql = lane & 7;
#pragma unroll 1
    for (int i = 0; i < 8; i++) {
        int n = nb + warp * 8 + i;
        int beg = g_off[n], end = g_off[n + 1];
        float ax = 0.f, ay = 0.f, az = 0.f, aw = 0.f;
#pragma unroll 1
        for (int e = beg + g; e < end; e += 4) {
            int s = g_ssrc[e];
            float4 v = x4[s * 8 + ql];
            ax += v.x; ay += v.y; az += v.z; aw += v.w;
        }
#pragma unroll
        for (int off = 8; off <= 16; off <<= 1) {
            ax += __shfl_xor_sync(0xffffffffu, ax, off);
            ay += __shfl_xor_sync(0xffffffffu, ay, off);
            az += __shfl_xor_sync(0xffffffffu, az, off);
            aw += __shfl_xor_sync(0xffffffffu, aw, off);
        }
        if (g == 0) {
            float r = 1.0f / fmaxf((float)(end - beg), 1.0f);
            int nl = warp * 8 + i;
            sacc[(ql * 4 + 0) * 68 + nl] = ax * r;
            sacc[(ql * 4 + 1) * 68 + nl] = ay * r;
            sacc[(ql * 4 + 2) * 68 + nl] = az * r;
            sacc[(ql * 4 + 3) * 68 + nl] = aw * r;
        }
    }
    __syncthreads();

    // GEMM: out[n][j] = sum_k sacc[k][n] * Ws[k][j] + b, with packed FFMA2
    int tx = tid & 15, ty = tid >> 4;
    unsigned long long acc2[4][2];
    {
        unsigned long long b01 = pack2(bsh[tx * 4 + 0], bsh[tx * 4 + 1]);
        unsigned long long b23 = pack2(bsh[tx * 4 + 2], bsh[tx * 4 + 3]);
#pragma unroll
        for (int i = 0; i < 4; i++) { acc2[i][0] = b01; acc2[i][1] = b23; }
    }
#pragma unroll 8
    for (int k = 0; k < 64; k++) {
        float4  a  = *(const float4*)&sacc[k * 68 + ty * 4];
        double2 wd = *(const double2*)&Ws[k * 68 + tx * 4];
        unsigned long long w01 = __double_as_longlong(wd.x);
        unsigned long long w23 = __double_as_longlong(wd.y);
        unsigned long long p;
        p = pack2(a.x, a.x); ffma2(acc2[0][0], p, w01); ffma2(acc2[0][1], p, w23);
        p = pack2(a.y, a.y); ffma2(acc2[1][0], p, w01); ffma2(acc2[1][1], p, w23);
        p = pack2(a.z, a.z); ffma2(acc2[2][0], p, w01); ffma2(acc2[2][1], p, w23);
        p = pack2(a.w, a.w); ffma2(acc2[3][0], p, w01); ffma2(acc2[3][1], p, w23);
    }
#pragma unroll
    for (int i = 0; i < 4; i++) {
        float2 p0 = unpack2(acc2[i][0]);
        float2 p1 = unpack2(acc2[i][1]);
        float4 o;
        o.x = fmaxf(p0.x, 0.f); o.y = fmaxf(p0.y, 0.f);
        o.z = fmaxf(p1.x, 0.f); o.w = fmaxf(p1.y, 0.f);
        ((float4*)g_h1)[(nb + ty * 4 + i) * 16 + tx] = o;
    }
}

// ---------------- fused layer 2: CSR gather-mean + GEMM + relu + pool --------
// dynamic smem: Ws[128][68] | sacc[128][68] | bsh[64] | wlin[128]
__global__ void __launch_bounds__(256) fused2_kernel(
        const float* __restrict__ W2l,
        const float* __restrict__ b2,
        const float* __restrict__ W2r,
        const float* __restrict__ Wlin,
        const int* __restrict__ batch,
        float* __restrict__ out) {
    extern __shared__ __align__(16) float sm[];
    float* Ws   = sm;                // 128*68
    float* sacc = sm + 128 * 68;     // 128*68 ; later reused as hs[64][68]
    float* bsh  = sacc + 128 * 68;   // 64
    float* wlin = bsh + 64;          // 128

    int tid = threadIdx.x;
    int nb = blockIdx.x * 64;

    for (int idx = tid; idx < 4096; idx += 256) {
        int j = idx >> 6, k = idx & 63;
        Ws[k * 68 + j]        = W2l[idx];
        Ws[(k + 64) * 68 + j] = W2r[idx];
    }
    if (tid < 64)  bsh[tid]  = b2[tid];
    if (tid < 128) wlin[tid] = Wlin[tid];

    const float4* h4 = (const float4*)g_h1;
    for (int idx = tid; idx < 1024; idx += 256) {
        int n = idx >> 4, q = idx & 15;
        float4 v = h4[(nb + n) * 16 + q];
        sacc[(64 + q * 4 + 0) * 68 + n] = v.x;
        sacc[(64 + q * 4 + 1) * 68 + n] = v.y;
        sacc[(64 + q * 4 + 2) * 68 + n] = v.z;
        sacc[(64 + q * 4 + 3) * 68 + n] = v.w;
    }

    int warp = tid >> 5, lane = tid & 31;
    int g = lane >> 3, ql = lane & 7;
#pragma unroll 1
    for (int i = 0; i < 8; i++) {
        int n = nb + warp * 8 + i;
        int beg = g_off[n], end = g_off[n + 1];
        float a0x = 0.f, a0y = 0.f, a0z = 0.f, a0w = 0.f;
        float a1x = 0.f, a1y = 0.f, a1z = 0.f, a1w = 0.f;
#pragma unroll 1
        for (int e = beg + g; e < end; e += 4) {
            int s = g_ssrc[e];
            float4 v0 = h4[s * 16 + ql];
            float4 v1 = h4[s * 16 + 8 + ql];
            a0x += v0.x; a0y += v0.y; a0z += v0.z; a0w += v0.w;
            a1x += v1.x; a1y += v1.y; a1z += v1.z; a1w += v1.w;
        }
#pragma unroll
        for (int off = 8; off <= 16; off <<= 1) {
            a0x += __shfl_xor_sync(0xffffffffu, a0x, off);
            a0y += __shfl_xor_sync(0xffffffffu, a0y, off);
            a0z += __shfl_xor_sync(0xffffffffu, a0z, off);
            a0w += __shfl_xor_sync(0xffffffffu, a0w, off);
            a1x += __shfl_xor_sync(0xffffffffu, a1x, off);
            a1y += __shfl_xor_sync(0xffffffffu, a1y, off);
            a1z += __shfl_xor_sync(0xffffffffu, a1z, off);
            a1w += __shfl_xor_sync(0xffffffffu, a1w, off);
        }
        if (g == 0) {
            float r = 1.0f / fmaxf((float)(end - beg), 1.0f);
            int nl = warp * 8 + i;
            sacc[(ql * 4 + 0) * 68 + nl] = a0x * r;
            sacc[(ql * 4 + 1) * 68 + nl] = a0y * r;
            sacc[(ql * 4 + 2) * 68 + nl] = a0z * r;
            sacc[(ql * 4 + 3) * 68 + nl] = a0w * r;
            sacc[(32 + ql * 4 + 0) * 68 + nl] = a1x * r;
            sacc[(32 + ql * 4 + 1) * 68 + nl] = a1y * r;
            sacc[(32 + ql * 4 + 2) * 68 + nl] = a1z * r;
            sacc[(32 + ql * 4 + 3) * 68 + nl] = a1w * r;
        }
    }
    __syncthreads();

    int tx = tid & 15, ty = tid >> 4;
    unsigned long long acc2[4][2];
    {
        unsigned long long b01 = pack2(bsh[tx * 4 + 0], bsh[tx * 4 + 1]);
        unsigned long long b23 = pack2(bsh[tx * 4 + 2], bsh[tx * 4 + 3]);
#pragma unroll
        for (int i = 0; i < 4; i++) { acc2[i][0] = b01; acc2[i][1] = b23; }
    }
#pragma unroll 8
    for (int k = 0; k < 128; k++) {
        float4  a  = *(const float4*)&sacc[k * 68 + ty * 4];
        double2 wd = *(const double2*)&Ws[k * 68 + tx * 4];
        unsigned long long w01 = __double_as_longlong(wd.x);
        unsigned long long w23 = __double_as_longlong(wd.y);
        unsigned long long p;
        p = pack2(a.x, a.x); ffma2(acc2[0][0], p, w01); ffma2(acc2[0][1], p, w23);
        p = pack2(a.y, a.y); ffma2(acc2[1][0], p, w01); ffma2(acc2[1][1], p, w23);
        p = pack2(a.z, a.z); ffma2(acc2[2][0], p, w01); ffma2(acc2[2][1], p, w23);
        p = pack2(a.w, a.w); ffma2(acc2[3][0], p, w01); ffma2(acc2[3][1], p, w23);
    }
    __syncthreads();   // all GEMM reads of sacc done before reuse as hs

    // write relu(h2) into hs[n][k] = sacc[n*68 + k]
#pragma unroll
    for (int i = 0; i < 4; i++) {
        float2 p0 = unpack2(acc2[i][0]);
        float2 p1 = unpack2(acc2[i][1]);
        float4 o;
        o.x = fmaxf(p0.x, 0.f); o.y = fmaxf(p0.y, 0.f);
        o.z = fmaxf(p1.x, 0.f); o.w = fmaxf(p1.y, 0.f);
        *(float4*)&sacc[(ty * 4 + i) * 68 + tx * 4] = o;
    }
    __syncthreads();

    // fused global mean pool + linear head: 2 atomics per node
    if (tid < 128) {
        int n = tid >> 1, o = tid & 1;
        float y = 0.f;
#pragma unroll 8
        for (int k = 0; k < 64; k++)
            y += sacc[n * 68 + k] * wlin[o * 64 + k];
        int gg = batch[nb + n];
        float c = fmaxf(g_cnt[gg], 1.0f);
        red_add_f32(&out[gg * 2 + o], y / c);
    }
}

// ---------------- launch -----------------------------------------------------
extern "C" void kernel_launch(void* const* d_in, const int* in_sizes, int n_in,
                              void* d_out, int out_size) {
    (void)in_sizes; (void)n_in; (void)out_size;
    const float* x    = (const float*)d_in[0];
    const int*   ei   = (const int*)d_in[1];
    const int*   batch= (const int*)d_in[2];
    const float* W1l  = (const float*)d_in[3];
    const float* b1   = (const float*)d_in[4];
    const float* W1r  = (const float*)d_in[5];
    const float* W2l  = (const float*)d_in[6];
    const float* b2   = (const float*)d_in[7];
    const float* W2r  = (const float*)d_in[8];
    const float* Wlin = (const float*)d_in[9];
    const float* blin = (const float*)d_in[10];
    float* out = (float*)d_out;

    const int* src = ei;
    const int* dst = ei + N_EDGES;

    const int SMEM2 = (2 * 128 * 68 + 64 + 128) * 4;   // 70400 B
    cudaFuncSetAttribute(fused2_kernel, cudaFuncAttributeMaxDynamicSharedMemorySize, SMEM2);

    init_kernel<<<(N_NODES / 4 + 255) / 256, 256>>>(out, blin);
    cnt_kernel<<<(N_NODES / 4 + 255) / 256, 256>>>(batch);
    hist_kernel<<<(N_EDGES / 4 + 255) / 256, 256>>>(dst);
    scanA_kernel<<<SCAN_BLOCKS, 256>>>();
    scanB_kernel<<<1, 256>>>();
    scanC_kernel<<<SCAN_BLOCKS, 256>>>();
    scatter_kernel<<<(N_EDGES / 4 + 255) / 256, 256>>>(src, dst);
    fused1_kernel<<<NTILES, 256>>>(x, W1l, b1, W1r);
    fused2_kernel<<<NTILES, 256, SMEM2>>>(W2l, b2, W2r, Wlin, batch, out);
}

// round 8
// speedup vs baseline: 1.2826x; 1.0838x over previous
#include <cuda_runtime.h>

#define N_NODES  200000
#define N_GRAPHS 4000
#define N_EDGES  3200000
#define NTILES   3125        /* N_NODES / 64 */
#define SCAN_BLOCKS 196      /* ceil(N_NODES / 1024) */

// ---------------- scratch (device globals; no allocation allowed) -----------
__device__ int   g_hcnt[N_NODES];
__device__ int   g_off[N_NODES + 1];
__device__ int   g_cur[N_NODES];
__device__ int   g_bsum[SCAN_BLOCKS];
__device__ int   g_bbase[SCAN_BLOCKS];
__device__ int   g_scancnt;
__device__ int   g_ssrc[N_EDGES];
__device__ float g_cnt[N_GRAPHS];
__device__ __align__(16) float g_h1[N_NODES * 64];

// ---------------- asm helpers ------------------------------------------------
__device__ __forceinline__ void red_add_f32(float* p, float v) {
    unsigned long long gp = (unsigned long long)__cvta_generic_to_global((void*)p);
    asm volatile("red.global.add.f32 [%0], %1;" :: "l"(gp), "f"(v) : "memory");
}
__device__ __forceinline__ void red_add_u32(int* p, unsigned v) {
    unsigned long long gp = (unsigned long long)__cvta_generic_to_global((void*)p);
    asm volatile("red.global.add.u32 [%0], %1;" :: "l"(gp), "r"(v) : "memory");
}
__device__ __forceinline__ unsigned long long pack2(float lo, float hi) {
    unsigned long long r;
    asm("mov.b64 %0, {%1, %2};" : "=l"(r) : "f"(lo), "f"(hi));
    return r;
}
__device__ __forceinline__ float2 unpack2(unsigned long long v) {
    float2 r;
    asm("mov.b64 {%0, %1}, %2;" : "=f"(r.x), "=f"(r.y) : "l"(v));
    return r;
}
__device__ __forceinline__ void ffma2(unsigned long long& acc,
                                      unsigned long long a, unsigned long long b) {
    asm("fma.rn.f32x2 %0, %1, %2, %0;" : "+l"(acc) : "l"(a), "l"(b));
}

// ---------------- init + graph-count (one node pass) --------------------------
__global__ void initcnt_kernel(float* __restrict__ out,
                               const float* __restrict__ b_lin,
                               const int* __restrict__ batch) {
    int i = blockIdx.x * blockDim.x + threadIdx.x;
    if (i < N_NODES / 4)  ((int4*)g_hcnt)[i] = make_int4(0, 0, 0, 0);
    if (i < N_GRAPHS / 4) ((float4*)g_cnt)[i] = make_float4(0.f, 0.f, 0.f, 0.f);
    if (i < N_GRAPHS * 2) out[i] = b_lin[i & 1];
    if (i == 0) g_scancnt = 0;
}

// batch is sorted: aggregate runs within each int4 before RED
__global__ void cnt_kernel(const int* __restrict__ batch) {
    int i = blockIdx.x * blockDim.x + threadIdx.x;
    if (i >= N_NODES / 4) return;
    int4 b = ((const int4*)batch)[i];
    int gcur = b.x; float c = 1.f;
    int v[3] = {b.y, b.z, b.w};
#pragma unroll
    for (int k = 0; k < 3; k++) {
        if (v[k] == gcur) c += 1.f;
        else { red_add_f32(&g_cnt[gcur], c); gcur = v[k]; c = 1.f; }
    }
    red_add_f32(&g_cnt[gcur], c);
}

// ---------------- CSR build: hist -> scan -> scatter -------------------------
__global__ void hist_kernel(const int* __restrict__ dst) {
    int i = blockIdx.x * blockDim.x + threadIdx.x;
    if (i >= N_EDGES / 4) return;
    int4 d = ((const int4*)dst)[i];
    red_add_u32(&g_hcnt[d.x], 1u);
    red_add_u32(&g_hcnt[d.y], 1u);
    red_add_u32(&g_hcnt[d.z], 1u);
    red_add_u32(&g_hcnt[d.w], 1u);
}

// scanA + scanB fused: per-block totals; last block to finish scans the totals.
__global__ void scanAB_kernel() {
    __shared__ int sh[256];
    __shared__ int is_last;
    int b = blockIdx.x, t = threadIdx.x;
    int i0 = b * 1024 + t * 4, s = 0;
#pragma unroll
    for (int i = 0; i < 4; i++) {
        int idx = i0 + i;
        s += (idx < N_NODES) ? g_hcnt[idx] : 0;
    }
    sh[t] = s; __syncthreads();
    for (int d = 128; d > 0; d >>= 1) {
        if (t < d) sh[t] += sh[t + d];
        __syncthreads();
    }
    if (t == 0) {
        g_bsum[b] = sh[0];
        __threadfence();
        int done = atomicAdd(&g_scancnt, 1);
        is_last = (done == SCAN_BLOCKS - 1) ? 1 : 0;
    }
    __syncthreads();
    if (is_last) {
        // exclusive scan of the 196 block totals
        sh[t] = (t < SCAN_BLOCKS) ? g_bsum[t] : 0;
        __syncthreads();
        for (int d = 1; d < 256; d <<= 1) {
            int u = (t >= d) ? sh[t - d] : 0;
            __syncthreads();
            sh[t] += u;
            __syncthreads();
        }
        if (t < SCAN_BLOCKS) g_bbase[t] = t ? sh[t - 1] : 0;
        if (t == 0) g_off[N_NODES] = N_EDGES;
    }
}

__global__ void scanC_kernel() {   // final offsets + cursor copy
    __shared__ int sh[256];
    int b = blockIdx.x, t = threadIdx.x;
    int i0 = b * 1024 + t * 4;
    int c[4], s = 0;
#pragma unroll
    for (int i = 0; i < 4; i++) {
        int idx = i0 + i;
        c[i] = (idx < N_NODES) ? g_hcnt[idx] : 0;
        s += c[i];
    }
    sh[t] = s; __syncthreads();
    for (int d = 1; d < 256; d <<= 1) {
        int u = (t >= d) ? sh[t - d] : 0;
        __syncthreads();
        sh[t] += u;
        __syncthreads();
    }
    int run = g_bbase[b] + (t ? sh[t - 1] : 0);
#pragma unroll
    for (int i = 0; i < 4; i++) {
        int idx = i0 + i;
        if (idx < N_NODES) {
            g_off[idx] = run;
            g_cur[idx] = run;
            run += c[i];
        }
    }
}

__global__ void scatter_kernel(const int* __restrict__ src,
                               const int* __restrict__ dst) {
    int i = blockIdx.x * blockDim.x + threadIdx.x;
    if (i >= N_EDGES / 4) return;
    int4 s = ((const int4*)src)[i];
    int4 d = ((const int4*)dst)[i];
    g_ssrc[atomicAdd(&g_cur[d.x], 1)] = s.x;
    g_ssrc[atomicAdd(&g_cur[d.y], 1)] = s.y;
    g_ssrc[atomicAdd(&g_cur[d.z], 1)] = s.z;
    g_ssrc[atomicAdd(&g_cur[d.w], 1)] = s.w;
}

// ---------------- fused layer 1: CSR gather-mean + GEMM + relu ---------------
// block = 256 threads, 64-node tile. Warp w owns nodes [w*8, w*8+8).
// Gather: 4 lane-groups of 8; group g handles edges beg+g, beg+g+4, ...
// e-loop unrolled x2 with independent accumulators -> 2 gather chains in flight.
__global__ void __launch_bounds__(256) fused1_kernel(
        const float* __restrict__ x,
        const float* __restrict__ W1l,
        const float* __restrict__ b1,
        const float* __restrict__ W1r) {
    __shared__ __align__(16) float Ws[64 * 68];
    __shared__ __align__(16) float sacc[64 * 68];
    __shared__ float bsh[64];

    int tid = threadIdx.x;
    int nb = blockIdx.x * 64;

    for (int idx = tid; idx < 2048; idx += 256) {
        int j = idx >> 5, k = idx & 31;
        Ws[k * 68 + j]        = W1l[idx];
        Ws[(k + 32) * 68 + j] = W1r[idx];
    }
    if (tid < 64) bsh[tid] = b1[tid];

    const float4* x4 = (const float4*)x;
    for (int idx = tid; idx < 512; idx += 256) {
        int n = idx >> 3, q = idx & 7;
        float4 v = x4[(nb + n) * 8 + q];
        sacc[(32 + q * 4 + 0) * 68 + n] = v.x;
        sacc[(32 + q * 4 + 1) * 68 + n] = v.y;
        sacc[(32 + q * 4 + 2) * 68 + n] = v.z;
        sacc[(32 + q * 4 + 3) * 68 + n] = v.w;
    }

    int warp = tid >> 5, lane = tid & 31;
    int g = lane >> 3, ql = lane & 7;
#pragma unroll 1
    for (int i = 0; i < 8; i++) {
        int n = nb + warp * 8 + i;
        int beg = g_off[n], end = g_off[n + 1];
        float ax = 0.f, ay = 0.f, az = 0.f, aw = 0.f;
        float bx = 0.f, by = 0.f, bz = 0.f, bw = 0.f;
        int e = beg + g;
#pragma unroll 1
        for (; e + 4 < end; e += 8) {
            int s0 = g_ssrc[e];
            int s1 = g_ssrc[e + 4];
            float4 v0 = x4[s0 * 8 + ql];
            float4 v1 = x4[s1 * 8 + ql];
            ax += v0.x; ay += v0.y; az += v0.z; aw += v0.w;
            bx += v1.x; by += v1.y; bz += v1.z; bw += v1.w;
        }
        if (e < end) {
            int s0 = g_ssrc[e];
            float4 v0 = x4[s0 * 8 + ql];
            ax += v0.x; ay += v0.y; az += v0.z; aw += v0.w;
        }
        ax += bx; ay += by; az += bz; aw += bw;
#pragma unroll
        for (int off = 8; off <= 16; off <<= 1) {
            ax += __shfl_xor_sync(0xffffffffu, ax, off);
            ay += __shfl_xor_sync(0xffffffffu, ay, off);
            az += __shfl_xor_sync(0xffffffffu, az, off);
            aw += __shfl_xor_sync(0xffffffffu, aw, off);
        }
        if (g == 0) {
            float r = 1.0f / fmaxf((float)(end - beg), 1.0f);
            int nl = warp * 8 + i;
            sacc[(ql * 4 + 0) * 68 + nl] = ax * r;
            sacc[(ql * 4 + 1) * 68 + nl] = ay * r;
            sacc[(ql * 4 + 2) * 68 + nl] = az * r;
            sacc[(ql * 4 + 3) * 68 + nl] = aw * r;
        }
    }
    __syncthreads();

    // GEMM: out[n][j] = sum_k sacc[k][n] * Ws[k][j] + b, with packed FFMA2
    int tx = tid & 15, ty = tid >> 4;
    unsigned long long acc2[4][2];
    {
        unsigned long long b01 = pack2(bsh[tx * 4 + 0], bsh[tx * 4 + 1]);
        unsigned long long b23 = pack2(bsh[tx * 4 + 2], bsh[tx * 4 + 3]);
#pragma unroll
        for (int i = 0; i < 4; i++) { acc2[i][0] = b01; acc2[i][1] = b23; }
    }
#pragma unroll 8
    for (int k = 0; k < 64; k++) {
        float4  a  = *(const float4*)&sacc[k * 68 + ty * 4];
        double2 wd = *(const double2*)&Ws[k * 68 + tx * 4];
        unsigned long long w01 = __double_as_longlong(wd.x);
        unsigned long long w23 = __double_as_longlong(wd.y);
        unsigned long long p;
        p = pack2(a.x, a.x); ffma2(acc2[0][0], p, w01); ffma2(acc2[0][1], p, w23);
        p = pack2(a.y, a.y); ffma2(acc2[1][0], p, w01); ffma2(acc2[1][1], p, w23);
        p = pack2(a.z, a.z); ffma2(acc2[2][0], p, w01); ffma2(acc2[2][1], p, w23);
        p = pack2(a.w, a.w); ffma2(acc2[3][0], p, w01); ffma2(acc2[3][1], p, w23);
    }
#pragma unroll
    for (int i = 0; i < 4; i++) {
        float2 p0 = unpack2(acc2[i][0]);
        float2 p1 = unpack2(acc2[i][1]);
        float4 o;
        o.x = fmaxf(p0.x, 0.f); o.y = fmaxf(p0.y, 0.f);
        o.z = fmaxf(p1.x, 0.f); o.w = fmaxf(p1.y, 0.f);
        ((float4*)g_h1)[(nb + ty * 4 + i) * 16 + tx] = o;
    }
}

// ---------------- fused layer 2: CSR gather-mean + GEMM + relu + pool --------
// dynamic smem: Ws[128][68] | sacc[128][68] | bsh[64] | wlin[128]
__global__ void __launch_bounds__(256) fused2_kernel(
        const float* __restrict__ W2l,
        const float* __restrict__ b2,
        const float* __restrict__ W2r,
        const float* __restrict__ Wlin,
        const int* __restrict__ batch,
        float* __restrict__ out) {
    extern __shared__ __align__(16) float sm[];
    float* Ws   = sm;                // 128*68
    float* sacc = sm + 128 * 68;     // 128*68 ; later reused as hs[64][68]
    float* bsh  = sacc + 128 * 68;   // 64
    float* wlin = bsh + 64;          // 128

    int tid = threadIdx.x;
    int nb = blockIdx.x * 64;

    for (int idx = tid; idx < 4096; idx += 256) {
        int j = idx >> 6, k = idx & 63;
        Ws[k * 68 + j]        = W2l[idx];
        Ws[(k + 64) * 68 + j] = W2r[idx];
    }
    if (tid < 64)  bsh[tid]  = b2[tid];
    if (tid < 128) wlin[tid] = Wlin[tid];

    const float4* h4 = (const float4*)g_h1;
    for (int idx = tid; idx < 1024; idx += 256) {
        int n = idx >> 4, q = idx & 15;
        float4 v = h4[(nb + n) * 16 + q];
        sacc[(64 + q * 4 + 0) * 68 + n] = v.x;
        sacc[(64 + q * 4 + 1) * 68 + n] = v.y;
        sacc[(64 + q * 4 + 2) * 68 + n] = v.z;
        sacc[(64 + q * 4 + 3) * 68 + n] = v.w;
    }

    int warp = tid >> 5, lane = tid & 31;
    int g = lane >> 3, ql = lane & 7;
#pragma unroll 1
    for (int i = 0; i < 8; i++) {
        int n = nb + warp * 8 + i;
        int beg = g_off[n], end = g_off[n + 1];
        float a0x = 0.f, a0y = 0.f, a0z = 0.f, a0w = 0.f;
        float a1x = 0.f, a1y = 0.f, a1z = 0.f, a1w = 0.f;
        float b0x = 0.f, b0y = 0.f, b0z = 0.f, b0w = 0.f;
        float b1x = 0.f, b1y = 0.f, b1z = 0.f, b1w = 0.f;
        int e = beg + g;
#pragma unroll 1
        for (; e + 4 < end; e += 8) {
            int s0 = g_ssrc[e];
            int s1 = g_ssrc[e + 4];
            float4 u0 = h4[s0 * 16 + ql];
            float4 u1 = h4[s0 * 16 + 8 + ql];
            float4 w0 = h4[s1 * 16 + ql];
            float4 w1 = h4[s1 * 16 + 8 + ql];
            a0x += u0.x; a0y += u0.y; a0z += u0.z; a0w += u0.w;
            a1x += u1.x; a1y += u1.y; a1z += u1.z; a1w += u1.w;
            b0x += w0.x; b0y += w0.y; b0z += w0.z; b0w += w0.w;
            b1x += w1.x; b1y += w1.y; b1z += w1.z; b1w += w1.w;
        }
        if (e < end) {
            int s0 = g_ssrc[e];
            float4 u0 = h4[s0 * 16 + ql];
            float4 u1 = h4[s0 * 16 + 8 + ql];
            a0x += u0.x; a0y += u0.y; a0z += u0.z; a0w += u0.w;
            a1x += u1.x; a1y += u1.y; a1z += u1.z; a1w += u1.w;
        }
        a0x += b0x; a0y += b0y; a0z += b0z; a0w += b0w;
        a1x += b1x; a1y += b1y; a1z += b1z; a1w += b1w;
#pragma unroll
        for (int off = 8; off <= 16; off <<= 1) {
            a0x += __shfl_xor_sync(0xffffffffu, a0x, off);
            a0y += __shfl_xor_sync(0xffffffffu, a0y, off);
            a0z += __shfl_xor_sync(0xffffffffu, a0z, off);
            a0w += __shfl_xor_sync(0xffffffffu, a0w, off);
            a1x += __shfl_xor_sync(0xffffffffu, a1x, off);
            a1y += __shfl_xor_sync(0xffffffffu, a1y, off);
            a1z += __shfl_xor_sync(0xffffffffu, a1z, off);
            a1w += __shfl_xor_sync(0xffffffffu, a1w, off);
        }
        if (g == 0) {
            float r = 1.0f / fmaxf((float)(end - beg), 1.0f);
            int nl = warp * 8 + i;
            sacc[(ql * 4 + 0) * 68 + nl] = a0x * r;
            sacc[(ql * 4 + 1) * 68 + nl] = a0y * r;
            sacc[(ql * 4 + 2) * 68 + nl] = a0z * r;
            sacc[(ql * 4 + 3) * 68 + nl] = a0w * r;
            sacc[(32 + ql * 4 + 0) * 68 + nl] = a1x * r;
            sacc[(32 + ql * 4 + 1) * 68 + nl] = a1y * r;
            sacc[(32 + ql * 4 + 2) * 68 + nl] = a1z * r;
            sacc[(32 + ql * 4 + 3) * 68 + nl] = a1w * r;
        }
    }
    __syncthreads();

    int tx = tid & 15, ty = tid >> 4;
    unsigned long long acc2[4][2];
    {
        unsigned long long b01 = pack2(bsh[tx * 4 + 0], bsh[tx * 4 + 1]);
        unsigned long long b23 = pack2(bsh[tx * 4 + 2], bsh[tx * 4 + 3]);
#pragma unroll
        for (int i = 0; i < 4; i++) { acc2[i][0] = b01; acc2[i][1] = b23; }
    }
#pragma unroll 8
    for (int k = 0; k < 128; k++) {
        float4  a  = *(const float4*)&sacc[k * 68 + ty * 4];
        double2 wd = *(const double2*)&Ws[k * 68 + tx * 4];
        unsigned long long w01 = __double_as_longlong(wd.x);
        unsigned long long w23 = __double_as_longlong(wd.y);
        unsigned long long p;
        p = pack2(a.x, a.x); ffma2(acc2[0][0], p, w01); ffma2(acc2[0][1], p, w23);
        p = pack2(a.y, a.y); ffma2(acc2[1][0], p, w01); ffma2(acc2[1][1], p, w23);
        p = pack2(a.z, a.z); ffma2(acc2[2][0], p, w01); ffma2(acc2[2][1], p, w23);
        p = pack2(a.w, a.w); ffma2(acc2[3][0], p, w01); ffma2(acc2[3][1], p, w23);
    }
    __syncthreads();   // all GEMM reads of sacc done before reuse as hs

    // write relu(h2) into hs[n][k] = sacc[n*68 + k]
#pragma unroll
    for (int i = 0; i < 4; i++) {
        float2 p0 = unpack2(acc2[i][0]);
        float2 p1 = unpack2(acc2[i][1]);
        float4 o;
        o.x = fmaxf(p0.x, 0.f); o.y = fmaxf(p0.y, 0.f);
        o.z = fmaxf(p1.x, 0.f); o.w = fmaxf(p1.y, 0.f);
        *(float4*)&sacc[(ty * 4 + i) * 68 + tx * 4] = o;
    }
    __syncthreads();

    // fused global mean pool + linear head: 2 atomics per node
    if (tid < 128) {
        int n = tid >> 1, o = tid & 1;
        float y = 0.f;
#pragma unroll 8
        for (int k = 0; k < 64; k++)
            y += sacc[n * 68 + k] * wlin[o * 64 + k];
        int gg = batch[nb + n];
        float c = fmaxf(g_cnt[gg], 1.0f);
        red_add_f32(&out[gg * 2 + o], y / c);
    }
}

// ---------------- launch -----------------------------------------------------
extern "C" void kernel_launch(void* const* d_in, const int* in_sizes, int n_in,
                              void* d_out, int out_size) {
    (void)in_sizes; (void)n_in; (void)out_size;
    const float* x    = (const float*)d_in[0];
    const int*   ei   = (const int*)d_in[1];
    const int*   batch= (const int*)d_in[2];
    const float* W1l  = (const float*)d_in[3];
    const float* b1   = (const float*)d_in[4];
    const float* W1r  = (const float*)d_in[5];
    const float* W2l  = (const float*)d_in[6];
    const float* b2   = (const float*)d_in[7];
    const float* W2r  = (const float*)d_in[8];
    const float* Wlin = (const float*)d_in[9];
    const float* blin = (const float*)d_in[10];
    float* out = (float*)d_out;

    const int* src = ei;
    const int* dst = ei + N_EDGES;

    const int SMEM2 = (2 * 128 * 68 + 64 + 128) * 4;   // 70400 B
    cudaFuncSetAttribute(fused2_kernel, cudaFuncAttributeMaxDynamicSharedMemorySize, SMEM2);

    initcnt_kernel<<<(N_NODES / 4 + 255) / 256, 256>>>(out, blin, batch);
    cnt_kernel<<<(N_NODES / 4 + 255) / 256, 256>>>(batch);
    hist_kernel<<<(N_EDGES / 4 + 255) / 256, 256>>>(dst);
    scanAB_kernel<<<SCAN_BLOCKS, 256>>>();
    scanC_kernel<<<SCAN_BLOCKS, 256>>>();
    scatter_kernel<<<(N_EDGES / 4 + 255) / 256, 256>>>(src, dst);
    fused1_kernel<<<NTILES, 256>>>(x, W1l, b1, W1r);
    fused2_kernel<<<NTILES, 256, SMEM2>>>(W2l, b2, W2r, Wlin, batch, out);
}